// round 13
// baseline (speedup 1.0000x reference)
#include <cuda_runtime.h>
#include <cstdint>

#define N_NODES 16384
#define A_ANCH  256
#define D_LAT   32

// B fragments for mma.m16n8k8.tf32, fragment order, pre-split hi/lo:
//   g_Bfrag[((ks*4 + nt)*32 + lane)] = (b0_hi, b1_hi, b0_lo, b1_lo)
// b0 = Mscaled[ks*8 + lane%4][nt*8 + lane/4], b1 = +4 k-row.
__device__ float4 g_Bfrag[32 * 4 * 32];   // 64 KB
__device__ float  g_c[D_LAT];

// ---------------------------------------------------------------------------
// Kernel 1: precompute B fragments + c (validated).
// ---------------------------------------------------------------------------
__global__ __launch_bounds__(256) void precompute_kernel(
    const float* __restrict__ embeds,
    const float* __restrict__ W,
    const float* __restrict__ b,
    const int*   __restrict__ anchor_ids)
{
    __shared__ float Wsh[D_LAT * D_LAT];
    __shared__ float esh[32][32];
    __shared__ float Ms[32][33];
    __shared__ float ssh[D_LAT];

    const int t   = threadIdx.x;
    const int blk = blockIdx.x;
    const int j   = t & 31;

    if (blk < 8) {
        #pragma unroll
        for (int i = t; i < D_LAT * D_LAT; i += 256) Wsh[i] = W[i];
        for (int r = t >> 5; r < 32; r += 8) {
            int id = anchor_ids[blk * 32 + r];
            esh[r][j] = embeds[id * D_LAT + j];
        }
        __syncthreads();
        for (int r = t >> 5; r < 32; r += 8) {
            float acc = 0.f;
            #pragma unroll
            for (int d = 0; d < D_LAT; d++) acc += esh[r][d] * Wsh[d * D_LAT + j];
            Ms[r][j] = acc * (1.0f / 256.0f);
        }
        __syncthreads();
        #pragma unroll
        for (int i = 0; i < 2; i++) {
            int idx  = t + 256 * i;
            int lane = idx & 31;
            int nt   = (idx >> 5) & 3;
            int kl   = (idx >> 7) & 3;
            int krow = kl * 8 + (lane & 3);
            int col  = nt * 8 + (lane >> 2);
            float b0 = Ms[krow][col];
            float b1 = Ms[krow + 4][col];
            unsigned h0, h1, l0, l1;
            asm("cvt.rna.tf32.f32 %0, %1;" : "=r"(h0) : "f"(b0));
            asm("cvt.rna.tf32.f32 %0, %1;" : "=r"(h1) : "f"(b1));
            float r0 = b0 - __uint_as_float(h0);
            float r1 = b1 - __uint_as_float(h1);
            asm("cvt.rna.tf32.f32 %0, %1;" : "=r"(l0) : "f"(r0));
            asm("cvt.rna.tf32.f32 %0, %1;" : "=r"(l1) : "f"(r1));
            int ks = blk * 4 + kl;
            g_Bfrag[(ks * 4 + nt) * 32 + lane] =
                make_float4(__uint_as_float(h0), __uint_as_float(h1),
                            __uint_as_float(l0), __uint_as_float(l1));
        }
    } else {
        #pragma unroll
        for (int i = t; i < D_LAT * D_LAT; i += 256) Wsh[i] = W[D_LAT * D_LAT + i];
        if (t < D_LAT) ssh[t] = 0.f;
        __syncthreads();
        {
            int grp = t >> 5;
            float part = 0.f;
            #pragma unroll 4
            for (int i = 0; i < 32; i++)
                part += embeds[(grp * 32 + i) * D_LAT + j];
            atomicAdd(&ssh[j], part);
        }
        __syncthreads();
        if (t < D_LAT) {
            float acc = 0.f;
            #pragma unroll
            for (int d = 0; d < D_LAT; d++) acc += ssh[d] * Wsh[d * D_LAT + t];
            g_c[t] = b[t] + acc * (1.0f / 256.0f);
        }
    }
}

// ---------------------------------------------------------------------------
// Kernel 2: tensor GEMM out = dists^T @ M + c, mma.m16n8k8.tf32, 3-term split.
// 256 thr = 8 warps = 2 row-tiles (16 rows) x 4 k-groups (64 k = 8 ksteps).
// ALL A operands (8 steps x 4 scalars) prefetched before the PDL grid sync:
// the main loop touches zero DRAM. B frags L1-resident, double-buffered.
// Block covers 32 rows; grid 512. K-group merge via 12 KB smem.
// ---------------------------------------------------------------------------
#define MMA(AC, A0, A1, A2, A3, B0, B1)                                       \
    asm("mma.sync.aligned.m16n8k8.row.col.f32.tf32.tf32.f32 "                 \
        "{%0,%1,%2,%3},{%4,%5,%6,%7},{%8,%9},{%0,%1,%2,%3};"                  \
        : "+f"(AC[0]), "+f"(AC[1]), "+f"(AC[2]), "+f"(AC[3])                  \
        : "r"(A0), "r"(A1), "r"(A2), "r"(A3), "r"(B0), "r"(B1));

__global__ __launch_bounds__(256) void pnn_mma_kernel(
    const float* __restrict__ dists,   // [A, N]
    float*       __restrict__ out)     // [N, 32]
{
    __shared__ float red[3][2][32][16];   // 12 KB: k-groups 1..3 partials

    const int t     = threadIdx.x;
    const int lane  = t & 31;
    const int w     = t >> 5;
    const int rtile = w & 1;
    const int kg    = w >> 1;          // 0..3
    const int n0    = blockIdx.x * 32 + rtile * 16;

    const int rowA = n0 + (lane >> 2);
    const int colA = lane & 3;
    // k-group kg covers global k rows [kg*64, kg*64+64) -> 8 ksteps
    const float* pa = dists + (size_t)(kg * 64 + colA) * N_NODES + rowA;
    const size_t N4 = 4 * (size_t)N_NODES;

    // ---- prefetch ALL A operands (8 ksteps) before the PDL grid sync ----
    float fa[8][4];
    #pragma unroll
    for (int p = 0; p < 8; p++) {
        size_t o = (size_t)(p * 8) * N_NODES;
        fa[p][0] = pa[o];
        fa[p][1] = pa[o + 8];
        fa[p][2] = pa[o + N4];
        fa[p][3] = pa[o + N4 + 8];
    }

    cudaGridDependencySynchronize();

    // B fragments for this k-group (ksteps kg*8 .. kg*8+7)
    const float4* pb = g_Bfrag + (size_t)(kg * 8 * 4) * 32 + lane;
    float4 fbA[4], fbB[4];
    #pragma unroll
    for (int nt = 0; nt < 4; nt++) {
        fbA[nt] = pb[(0 * 4 + nt) << 5];
        fbB[nt] = pb[(1 * 4 + nt) << 5];
    }

    float acc[4][4];
    #pragma unroll
    for (int i = 0; i < 4; i++)
        #pragma unroll
        for (int k = 0; k < 4; k++) acc[i][k] = 0.f;

    #define STEP(u, FB) {                                                         \
        const int ks = it + (u);                                                  \
        unsigned ah[4], al[4];                                                    \
        _Pragma("unroll")                                                         \
        for (int i = 0; i < 4; i++) {                                             \
            float av = fa[ks][i];                                                 \
            asm("cvt.rna.tf32.f32 %0, %1;" : "=r"(ah[i]) : "f"(av));              \
            float lo = av - __uint_as_float(ah[i]);                               \
            asm("cvt.rna.tf32.f32 %0, %1;" : "=r"(al[i]) : "f"(lo));              \
        }                                                                         \
        _Pragma("unroll")                                                         \
        for (int nt = 0; nt < 4; nt++) {                                          \
            unsigned b0h = __float_as_uint(FB[nt].x);                             \
            unsigned b1h = __float_as_uint(FB[nt].y);                             \
            unsigned b0l = __float_as_uint(FB[nt].z);                             \
            unsigned b1l = __float_as_uint(FB[nt].w);                             \
            MMA(acc[nt], ah[0], ah[1], ah[2], ah[3], b0h, b1h);                   \
            MMA(acc[nt], ah[0], ah[1], ah[2], ah[3], b0l, b1l);                   \
            MMA(acc[nt], al[0], al[1], al[2], al[3], b0h, b1h);                   \
        }                                                                         \
        if (ks + 2 < 8) {                                                         \
            _Pragma("unroll")                                                     \
            for (int nt = 0; nt < 4; nt++)                                        \
                FB[nt] = pb[(((ks + 2) * 4 + nt) << 5)];                          \
        }                                                                         \
    }

    #pragma unroll
    for (int it = 0; it < 8; it += 4) {
        STEP(0, fbA)
        STEP(1, fbB)
        STEP(2, fbA)
        STEP(3, fbB)
    }
    #undef STEP

    // ---- merge the 4 k-groups ----
    if (kg != 0) {
        #pragma unroll
        for (int nt = 0; nt < 4; nt++)
            #pragma unroll
            for (int i = 0; i < 4; i++)
                red[kg - 1][rtile][lane][nt * 4 + i] = acc[nt][i];
    }
    __syncthreads();

    if (kg == 0) {
        #pragma unroll
        for (int g = 0; g < 3; g++)
            #pragma unroll
            for (int nt = 0; nt < 4; nt++)
                #pragma unroll
                for (int i = 0; i < 4; i++)
                    acc[nt][i] += red[g][rtile][lane][nt * 4 + i];

        const int r0 = n0 + (lane >> 2);
        #pragma unroll
        for (int nt = 0; nt < 4; nt++) {
            int col = nt * 8 + 2 * (lane & 3);
            float2 cc = *(const float2*)(g_c + col);
            float2 v0 = make_float2(acc[nt][0] + cc.x, acc[nt][1] + cc.y);
            float2 v1 = make_float2(acc[nt][2] + cc.x, acc[nt][3] + cc.y);
            *(float2*)(out + (size_t)r0 * D_LAT + col)       = v0;
            *(float2*)(out + (size_t)(r0 + 8) * D_LAT + col) = v1;
        }
    }
}

extern "C" void kernel_launch(void* const* d_in, const int* in_sizes, int n_in,
                              void* d_out, int out_size)
{
    const float* embeds     = (const float*)d_in[0];
    const float* dists      = (const float*)d_in[1];
    const float* W_hidden   = (const float*)d_in[2];
    const float* b_hidden   = (const float*)d_in[3];
    const int*   anchor_ids = (const int*)  d_in[4];
    float*       out        = (float*)d_out;

    precompute_kernel<<<9, 256>>>(embeds, W_hidden, b_hidden, anchor_ids);

    cudaLaunchConfig_t cfg = {};
    cfg.gridDim  = dim3(N_NODES / 32, 1, 1);
    cfg.blockDim = dim3(256, 1, 1);
    cfg.dynamicSmemBytes = 0;
    cfg.stream = 0;
    cudaLaunchAttribute attr[1];
    attr[0].id = cudaLaunchAttributeProgrammaticStreamSerialization;
    attr[0].val.programmaticStreamSerializationAllowed = 1;
    cfg.attrs = attr;
    cfg.numAttrs = 1;

    cudaError_t e = cudaLaunchKernelEx(&cfg, pnn_mma_kernel, dists, out);
    if (e != cudaSuccess) {
        pnn_mma_kernel<<<N_NODES / 32, 256>>>(dists, out);
    }
}

// round 14
// speedup vs baseline: 1.0021x; 1.0021x over previous
#include <cuda_runtime.h>
#include <cstdint>

#define N_NODES 16384
#define A_ANCH  256
#define D_LAT   32

// B fragments for mma.m16n8k8.tf32, fragment order, pre-split hi/lo:
//   g_Bfrag[((ks*4 + nt)*32 + lane)] = (b0_hi, b1_hi, b0_lo, b1_lo)
__device__ float4 g_Bfrag[32 * 4 * 32];   // 64 KB
__device__ float  g_c[D_LAT];

// ---------------------------------------------------------------------------
// Kernel 1: precompute B fragments + c.
// ---------------------------------------------------------------------------
__global__ __launch_bounds__(256) void precompute_kernel(
    const float* __restrict__ embeds,
    const float* __restrict__ W,
    const float* __restrict__ b,
    const int*   __restrict__ anchor_ids)
{
    __shared__ float Wsh[D_LAT * D_LAT];
    __shared__ float esh[32][32];
    __shared__ float Ms[32][33];
    __shared__ float ssh[D_LAT];

    const int t   = threadIdx.x;
    const int blk = blockIdx.x;
    const int j   = t & 31;

    if (blk < 8) {
        #pragma unroll
        for (int i = t; i < D_LAT * D_LAT; i += 256) Wsh[i] = W[i];
        for (int r = t >> 5; r < 32; r += 8) {
            int id = anchor_ids[blk * 32 + r];
            esh[r][j] = embeds[id * D_LAT + j];
        }
        __syncthreads();
        for (int r = t >> 5; r < 32; r += 8) {
            float acc = 0.f;
            #pragma unroll
            for (int d = 0; d < D_LAT; d++) acc += esh[r][d] * Wsh[d * D_LAT + j];
            Ms[r][j] = acc * (1.0f / 256.0f);
        }
        __syncthreads();
        #pragma unroll
        for (int i = 0; i < 2; i++) {
            int idx  = t + 256 * i;
            int lane = idx & 31;
            int nt   = (idx >> 5) & 3;
            int kl   = (idx >> 7) & 3;
            int krow = kl * 8 + (lane & 3);
            int col  = nt * 8 + (lane >> 2);
            float b0 = Ms[krow][col];
            float b1 = Ms[krow + 4][col];
            unsigned h0, h1, l0, l1;
            asm("cvt.rna.tf32.f32 %0, %1;" : "=r"(h0) : "f"(b0));
            asm("cvt.rna.tf32.f32 %0, %1;" : "=r"(h1) : "f"(b1));
            float r0 = b0 - __uint_as_float(h0);
            float r1 = b1 - __uint_as_float(h1);
            asm("cvt.rna.tf32.f32 %0, %1;" : "=r"(l0) : "f"(r0));
            asm("cvt.rna.tf32.f32 %0, %1;" : "=r"(l1) : "f"(r1));
            int ks = blk * 4 + kl;
            g_Bfrag[(ks * 4 + nt) * 32 + lane] =
                make_float4(__uint_as_float(h0), __uint_as_float(h1),
                            __uint_as_float(l0), __uint_as_float(l1));
        }
    } else {
        #pragma unroll
        for (int i = t; i < D_LAT * D_LAT; i += 256) Wsh[i] = W[D_LAT * D_LAT + i];
        if (t < D_LAT) ssh[t] = 0.f;
        __syncthreads();
        {
            int grp = t >> 5;
            float part = 0.f;
            #pragma unroll            // FULL unroll: 32 independent loads (MLP 32)
            for (int i = 0; i < 32; i++)
                part += embeds[(grp * 32 + i) * D_LAT + j];
            atomicAdd(&ssh[j], part);
        }
        __syncthreads();
        if (t < D_LAT) {
            float acc = 0.f;
            #pragma unroll
            for (int d = 0; d < D_LAT; d++) acc += ssh[d] * Wsh[d * D_LAT + t];
            g_c[t] = b[t] + acc * (1.0f / 256.0f);
        }
    }
}

// ---------------------------------------------------------------------------
// Kernel 2: tensor GEMM out = dists^T @ M + c, mma.m16n8k8.tf32, 3-term split.
// 256 thr = 8 warps = 2 row-tiles (16 rows) x 4 k-groups (64 k = 8 ksteps).
// A tile (256 k x 32 n = 32 KB) staged via cp.async issued BEFORE the PDL
// grid sync (register-free, max MLP). Main loop: conflict-free LDS + MMA,
// zero DRAM. Reduction reuses the A smem. Grid 512, ~3 blocks/SM.
// ---------------------------------------------------------------------------
#define AT_STRIDE 40                      // floats per k-row (32 n + 8 pad)
#define AT_BYTES  (256 * AT_STRIDE * 4)   // 40960

#define MMA(AC, A0, A1, A2, A3, B0, B1)                                       \
    asm("mma.sync.aligned.m16n8k8.row.col.f32.tf32.tf32.f32 "                 \
        "{%0,%1,%2,%3},{%4,%5,%6,%7},{%8,%9},{%0,%1,%2,%3};"                  \
        : "+f"(AC[0]), "+f"(AC[1]), "+f"(AC[2]), "+f"(AC[3])                  \
        : "r"(A0), "r"(A1), "r"(A2), "r"(A3), "r"(B0), "r"(B1));

__global__ __launch_bounds__(256) void pnn_mma_kernel(
    const float* __restrict__ dists,   // [A, N]
    float*       __restrict__ out)     // [N, 32]
{
    extern __shared__ __align__(16) float Asm[];   // [256][AT_STRIDE]; reused for reduce

    const int t     = threadIdx.x;
    const int lane  = t & 31;
    const int w     = t >> 5;
    const int rtile = w & 1;
    const int kg    = w >> 1;          // 0..3
    const int n0    = blockIdx.x * 32;

    uint32_t sbase;
    asm("{ .reg .u64 tmp; cvta.to.shared.u64 tmp, %1; cvt.u32.u64 %0, tmp; }"
        : "=r"(sbase) : "l"(Asm));

    // ---- stage A tile via cp.async (issued before the PDL grid sync) ----
    {
        const int chunk = t & 7;               // 16B chunk within 128B row
        const int krow0 = t >> 3;              // 0..31
        #pragma unroll
        for (int i = 0; i < 8; i++) {
            int krow = krow0 + 32 * i;
            const float* src = dists + (size_t)krow * N_NODES + n0 + chunk * 4;
            uint32_t dst = sbase + krow * (AT_STRIDE * 4) + chunk * 16;
            asm volatile("cp.async.ca.shared.global [%0], [%1], 16;"
                         :: "r"(dst), "l"(src) : "memory");
        }
        asm volatile("cp.async.commit_group;" ::: "memory");
    }

    // ---- wait for precompute results (PDL) ----
    cudaGridDependencySynchronize();

    // ---- B fragments for this k-group (ksteps kg*8 .. kg*8+7) ----
    const float4* pb = g_Bfrag + (size_t)(kg * 8 * 4) * 32 + lane;
    float4 fbA[4], fbB[4];
    #pragma unroll
    for (int nt = 0; nt < 4; nt++) {
        fbA[nt] = pb[(0 * 4 + nt) << 5];
        fbB[nt] = pb[(1 * 4 + nt) << 5];
    }

    // ---- A staging complete ----
    asm volatile("cp.async.wait_group 0;" ::: "memory");
    __syncthreads();

    float acc[4][4];
    #pragma unroll
    for (int i = 0; i < 4; i++)
        #pragma unroll
        for (int k = 0; k < 4; k++) acc[i][k] = 0.f;

    const int rn = rtile * 16 + (lane >> 2);   // local n row for a0/a2
    const int c  = lane & 3;

    #define STEP(u, FB) {                                                         \
        const int ks = it + (u);                                                  \
        const int K0 = kg * 64 + ks * 8;                                          \
        float av0 = Asm[(K0 + c) * AT_STRIDE + rn];                               \
        float av1 = Asm[(K0 + c) * AT_STRIDE + rn + 8];                           \
        float av2 = Asm[(K0 + c + 4) * AT_STRIDE + rn];                           \
        float av3 = Asm[(K0 + c + 4) * AT_STRIDE + rn + 8];                       \
        unsigned ah[4], al[4];                                                    \
        float av[4] = {av0, av1, av2, av3};                                       \
        _Pragma("unroll")                                                         \
        for (int i = 0; i < 4; i++) {                                             \
            asm("cvt.rna.tf32.f32 %0, %1;" : "=r"(ah[i]) : "f"(av[i]));           \
            float lo = av[i] - __uint_as_float(ah[i]);                            \
            asm("cvt.rna.tf32.f32 %0, %1;" : "=r"(al[i]) : "f"(lo));              \
        }                                                                         \
        _Pragma("unroll")                                                         \
        for (int nt = 0; nt < 4; nt++) {                                          \
            unsigned b0h = __float_as_uint(FB[nt].x);                             \
            unsigned b1h = __float_as_uint(FB[nt].y);                             \
            unsigned b0l = __float_as_uint(FB[nt].z);                             \
            unsigned b1l = __float_as_uint(FB[nt].w);                             \
            MMA(acc[nt], ah[0], ah[1], ah[2], ah[3], b0h, b1h);                   \
            MMA(acc[nt], ah[0], ah[1], ah[2], ah[3], b0l, b1l);                   \
            MMA(acc[nt], al[0], al[1], al[2], al[3], b0h, b1h);                   \
        }                                                                         \
        if (ks + 2 < 8) {                                                         \
            _Pragma("unroll")                                                     \
            for (int nt = 0; nt < 4; nt++)                                        \
                FB[nt] = pb[(((ks + 2) * 4 + nt) << 5)];                          \
        }                                                                         \
    }

    #pragma unroll
    for (int it = 0; it < 8; it += 4) {
        STEP(0, fbA)
        STEP(1, fbB)
        STEP(2, fbA)
        STEP(3, fbB)
    }
    #undef STEP

    // ---- merge the 4 k-groups (reuse Asm as reduction buffer) ----
    __syncthreads();   // all A reads done
    float* red = Asm;  // [3][2][32][16]
    if (kg != 0) {
        #pragma unroll
        for (int nt = 0; nt < 4; nt++)
            #pragma unroll
            for (int i = 0; i < 4; i++)
                red[(((kg - 1) * 2 + rtile) * 32 + lane) * 16 + nt * 4 + i] = acc[nt][i];
    }
    __syncthreads();

    if (kg == 0) {
        #pragma unroll
        for (int g = 0; g < 3; g++)
            #pragma unroll
            for (int nt = 0; nt < 4; nt++)
                #pragma unroll
                for (int i = 0; i < 4; i++)
                    acc[nt][i] += red[((g * 2 + rtile) * 32 + lane) * 16 + nt * 4 + i];

        const int r0 = n0 + rtile * 16 + (lane >> 2);
        #pragma unroll
        for (int nt = 0; nt < 4; nt++) {
            int col = nt * 8 + 2 * (lane & 3);
            float2 cc = *(const float2*)(g_c + col);
            float2 v0 = make_float2(acc[nt][0] + cc.x, acc[nt][1] + cc.y);
            float2 v1 = make_float2(acc[nt][2] + cc.x, acc[nt][3] + cc.y);
            *(float2*)(out + (size_t)r0 * D_LAT + col)       = v0;
            *(float2*)(out + (size_t)(r0 + 8) * D_LAT + col) = v1;
        }
    }
}

extern "C" void kernel_launch(void* const* d_in, const int* in_sizes, int n_in,
                              void* d_out, int out_size)
{
    const float* embeds     = (const float*)d_in[0];
    const float* dists      = (const float*)d_in[1];
    const float* W_hidden   = (const float*)d_in[2];
    const float* b_hidden   = (const float*)d_in[3];
    const int*   anchor_ids = (const int*)  d_in[4];
    float*       out        = (float*)d_out;

    cudaFuncSetAttribute(pnn_mma_kernel,
                         cudaFuncAttributeMaxDynamicSharedMemorySize, AT_BYTES);

    precompute_kernel<<<9, 256>>>(embeds, W_hidden, b_hidden, anchor_ids);

    cudaLaunchConfig_t cfg = {};
    cfg.gridDim  = dim3(N_NODES / 32, 1, 1);
    cfg.blockDim = dim3(256, 1, 1);
    cfg.dynamicSmemBytes = AT_BYTES;
    cfg.stream = 0;
    cudaLaunchAttribute attr[1];
    attr[0].id = cudaLaunchAttributeProgrammaticStreamSerialization;
    attr[0].val.programmaticStreamSerializationAllowed = 1;
    cfg.attrs = attr;
    cfg.numAttrs = 1;

    cudaError_t e = cudaLaunchKernelEx(&cfg, pnn_mma_kernel, dists, out);
    if (e != cudaSuccess) {
        pnn_mma_kernel<<<N_NODES / 32, 256, AT_BYTES>>>(dists, out);
    }
}

// round 15
// speedup vs baseline: 1.0172x; 1.0151x over previous
#include <cuda_runtime.h>
#include <cuda_fp16.h>
#include <cstdint>

#define N_NODES 16384
#define A_ANCH  256
#define D_LAT   32

// B fragments for mma.m16n8k16.f16 (M UNSCALED; 1/256 applied in epilogue):
//   g_Bfrag16[((ks*4 + nt)*32 + lane)] = {b0_hi, b1_hi, b0_lo, b1_lo} (packed half2)
//   b0 = {M[k0][col], M[k0+1][col]}, b1 = {M[k0+8][col], M[k0+9][col]}
//   k0 = ks*16 + 2*(lane&3), col = nt*8 + (lane>>2).
__device__ uint4 g_Bfrag16[16 * 4 * 32];   // 32 KB
__device__ float g_c[D_LAT];

#define PACK_H2(dst, flo, fhi) \
    asm("cvt.rn.f16x2.f32 %0, %1, %2;" : "=r"(dst) : "f"(fhi), "f"(flo))

__device__ __forceinline__ float2 h2f2(unsigned u) {
    __half2 h = *reinterpret_cast<__half2*>(&u);
    return __half22float2(h);
}

// ---------------------------------------------------------------------------
// Kernel 1: precompute fp16 B fragments (hi/lo split) + c.
// ---------------------------------------------------------------------------
__global__ __launch_bounds__(256) void precompute_kernel(
    const float* __restrict__ embeds,
    const float* __restrict__ W,       // [64,32]: W1 rows 0..31, W2 rows 32..63
    const float* __restrict__ b,
    const int*   __restrict__ anchor_ids)
{
    __shared__ float Wsh[D_LAT * D_LAT];
    __shared__ float esh[32][32];
    __shared__ float Ms[32][33];
    __shared__ float ssh[D_LAT];

    const int t   = threadIdx.x;
    const int blk = blockIdx.x;
    const int j   = t & 31;

    if (blk < 8) {
        #pragma unroll
        for (int i = t; i < D_LAT * D_LAT; i += 256) Wsh[i] = W[i];
        for (int r = t >> 5; r < 32; r += 8) {
            int id = anchor_ids[blk * 32 + r];
            esh[r][j] = embeds[id * D_LAT + j];
        }
        __syncthreads();
        for (int r = t >> 5; r < 32; r += 8) {
            float acc = 0.f;
            #pragma unroll
            for (int d = 0; d < D_LAT; d++) acc += esh[r][d] * Wsh[d * D_LAT + j];
            Ms[r][j] = acc;                      // UNSCALED
        }
        __syncthreads();
        // this block covers global ksteps 2*blk, 2*blk+1 (16 k-rows each)
        {
            int lane = t & 31;
            int nt   = (t >> 5) & 3;
            int kl   = t >> 7;                   // 0 or 1
            int k0l  = kl * 16 + 2 * (lane & 3);
            int col  = nt * 8 + (lane >> 2);
            float f0 = Ms[k0l][col];
            float f1 = Ms[k0l + 1][col];
            float f2 = Ms[k0l + 8][col];
            float f3 = Ms[k0l + 9][col];
            unsigned b0h, b1h, b0l, b1l;
            PACK_H2(b0h, f0, f1);
            PACK_H2(b1h, f2, f3);
            float2 r0 = h2f2(b0h), r1 = h2f2(b1h);
            PACK_H2(b0l, f0 - r0.x, f1 - r0.y);
            PACK_H2(b1l, f2 - r1.x, f3 - r1.y);
            int ks = 2 * blk + kl;
            g_Bfrag16[(ks * 4 + nt) * 32 + lane] = make_uint4(b0h, b1h, b0l, b1l);
        }
    } else {
        #pragma unroll
        for (int i = t; i < D_LAT * D_LAT; i += 256) Wsh[i] = W[D_LAT * D_LAT + i];
        if (t < D_LAT) ssh[t] = 0.f;
        __syncthreads();
        {
            int grp = t >> 5;
            float part = 0.f;
            #pragma unroll
            for (int i = 0; i < 32; i++)
                part += embeds[(grp * 32 + i) * D_LAT + j];
            atomicAdd(&ssh[j], part);
        }
        __syncthreads();
        if (t < D_LAT) {
            float acc = 0.f;
            #pragma unroll
            for (int d = 0; d < D_LAT; d++) acc += ssh[d] * Wsh[d * D_LAT + t];
            g_c[t] = b[t] + acc * (1.0f / 256.0f);
        }
    }
}

// ---------------------------------------------------------------------------
// Kernel 2: tensor GEMM out = (dists^T @ M)/256 + c via mma.m16n8k16.f16,
// 3-pass fp16 split. 256 thr = 8 warps = 2 row-tiles x 4 k-groups
// (64 k = 4 ksteps of 16). A tile staged via cp.async before the PDL sync.
// Grid 512 x 32 rows. K-group merge reuses A smem.
// ---------------------------------------------------------------------------
#define AT_STRIDE 36                      // floats per k-row (32 n + 4 pad)
#define AT_BYTES  (256 * AT_STRIDE * 4)   // 36864

#define MMAH(AC, A0, A1, A2, A3, B0, B1)                                      \
    asm("mma.sync.aligned.m16n8k16.row.col.f32.f16.f16.f32 "                  \
        "{%0,%1,%2,%3},{%4,%5,%6,%7},{%8,%9},{%0,%1,%2,%3};"                  \
        : "+f"(AC[0]), "+f"(AC[1]), "+f"(AC[2]), "+f"(AC[3])                  \
        : "r"(A0), "r"(A1), "r"(A2), "r"(A3), "r"(B0), "r"(B1));

__global__ __launch_bounds__(256) void pnn_mma_kernel(
    const float* __restrict__ dists,   // [A, N]
    float*       __restrict__ out)     // [N, 32]
{
    extern __shared__ __align__(16) float Asm[];   // [256][AT_STRIDE]

    const int t     = threadIdx.x;
    const int lane  = t & 31;
    const int w     = t >> 5;
    const int rtile = w & 1;
    const int kg    = w >> 1;          // 0..3
    const int n0    = blockIdx.x * 32;

    uint32_t sbase;
    asm("{ .reg .u64 tmp; cvta.to.shared.u64 tmp, %1; cvt.u32.u64 %0, tmp; }"
        : "=r"(sbase) : "l"(Asm));

    // ---- stage A tile (256 k x 32 n) via cp.async, before the PDL sync ----
    {
        const int chunk = t & 7;
        const int krow0 = t >> 3;
        #pragma unroll
        for (int i = 0; i < 8; i++) {
            int krow = krow0 + 32 * i;
            const float* src = dists + (size_t)krow * N_NODES + n0 + chunk * 4;
            uint32_t dst = sbase + krow * (AT_STRIDE * 4) + chunk * 16;
            asm volatile("cp.async.ca.shared.global [%0], [%1], 16;"
                         :: "r"(dst), "l"(src) : "memory");
        }
        asm volatile("cp.async.commit_group;" ::: "memory");
    }

    cudaGridDependencySynchronize();

    // ---- B fragments for this k-group (ksteps kg*4 .. kg*4+3) ----
    const uint4* pb = g_Bfrag16 + (size_t)(kg * 4 * 4) * 32 + lane;
    uint4 fbA[4], fbB[4];
    #pragma unroll
    for (int nt = 0; nt < 4; nt++) {
        fbA[nt] = pb[(0 * 4 + nt) << 5];
        fbB[nt] = pb[(1 * 4 + nt) << 5];
    }

    asm volatile("cp.async.wait_group 0;" ::: "memory");
    __syncthreads();

    float acc[4][4];
    #pragma unroll
    for (int i = 0; i < 4; i++)
        #pragma unroll
        for (int k = 0; k < 4; k++) acc[i][k] = 0.f;

    const int rn = rtile * 16 + (lane >> 2);
    const int c2 = 2 * (lane & 3);

    #define STEP(jj, FB) {                                                        \
        const int K0 = (kg * 4 + (jj)) * 16;                                      \
        float v00 = Asm[(K0 + c2)     * AT_STRIDE + rn];                          \
        float v01 = Asm[(K0 + c2 + 1) * AT_STRIDE + rn];                          \
        float v10 = Asm[(K0 + c2)     * AT_STRIDE + rn + 8];                      \
        float v11 = Asm[(K0 + c2 + 1) * AT_STRIDE + rn + 8];                      \
        float v20 = Asm[(K0 + c2 + 8) * AT_STRIDE + rn];                          \
        float v21 = Asm[(K0 + c2 + 9) * AT_STRIDE + rn];                          \
        float v30 = Asm[(K0 + c2 + 8) * AT_STRIDE + rn + 8];                      \
        float v31 = Asm[(K0 + c2 + 9) * AT_STRIDE + rn + 8];                      \
        unsigned ah0, ah1, ah2, ah3, al0, al1, al2, al3;                          \
        PACK_H2(ah0, v00, v01);                                                   \
        PACK_H2(ah1, v10, v11);                                                   \
        PACK_H2(ah2, v20, v21);                                                   \
        PACK_H2(ah3, v30, v31);                                                   \
        { float2 r = h2f2(ah0); PACK_H2(al0, v00 - r.x, v01 - r.y); }             \
        { float2 r = h2f2(ah1); PACK_H2(al1, v10 - r.x, v11 - r.y); }             \
        { float2 r = h2f2(ah2); PACK_H2(al2, v20 - r.x, v21 - r.y); }             \
        { float2 r = h2f2(ah3); PACK_H2(al3, v30 - r.x, v31 - r.y); }             \
        _Pragma("unroll")                                                         \
        for (int nt = 0; nt < 4; nt++) {                                          \
            MMAH(acc[nt], ah0, ah1, ah2, ah3, FB[nt].x, FB[nt].y);                \
            MMAH(acc[nt], ah0, ah1, ah2, ah3, FB[nt].z, FB[nt].w);                \
            MMAH(acc[nt], al0, al1, al2, al3, FB[nt].x, FB[nt].y);                \
        }                                                                         \
        if ((jj) + 2 < 4) {                                                       \
            _Pragma("unroll")                                                     \
            for (int nt = 0; nt < 4; nt++)                                        \
                FB[nt] = pb[((((jj) + 2) * 4 + nt) << 5)];                        \
        }                                                                         \
    }

    STEP(0, fbA)
    STEP(1, fbB)
    STEP(2, fbA)
    STEP(3, fbB)
    #undef STEP

    // ---- merge the 4 k-groups (reuse Asm) ----
    __syncthreads();
    float* red = Asm;   // [3][2][32][16] = 12 KB
    if (kg != 0) {
        #pragma unroll
        for (int nt = 0; nt < 4; nt++)
            #pragma unroll
            for (int i = 0; i < 4; i++)
                red[(((kg - 1) * 2 + rtile) * 32 + lane) * 16 + nt * 4 + i] = acc[nt][i];
    }
    __syncthreads();

    if (kg == 0) {
        #pragma unroll
        for (int g = 0; g < 3; g++)
            #pragma unroll
            for (int nt = 0; nt < 4; nt++)
                #pragma unroll
                for (int i = 0; i < 4; i++)
                    acc[nt][i] += red[((g * 2 + rtile) * 32 + lane) * 16 + nt * 4 + i];

        const int r0 = n0 + rtile * 16 + (lane >> 2);
        #pragma unroll
        for (int nt = 0; nt < 4; nt++) {
            int col = nt * 8 + 2 * (lane & 3);
            float2 cc = *(const float2*)(g_c + col);
            float2 v0 = make_float2(acc[nt][0] * (1.0f / 256.0f) + cc.x,
                                    acc[nt][1] * (1.0f / 256.0f) + cc.y);
            float2 v1 = make_float2(acc[nt][2] * (1.0f / 256.0f) + cc.x,
                                    acc[nt][3] * (1.0f / 256.0f) + cc.y);
            *(float2*)(out + (size_t)r0 * D_LAT + col)       = v0;
            *(float2*)(out + (size_t)(r0 + 8) * D_LAT + col) = v1;
        }
    }
}

extern "C" void kernel_launch(void* const* d_in, const int* in_sizes, int n_in,
                              void* d_out, int out_size)
{
    const float* embeds     = (const float*)d_in[0];
    const float* dists      = (const float*)d_in[1];
    const float* W_hidden   = (const float*)d_in[2];
    const float* b_hidden   = (const float*)d_in[3];
    const int*   anchor_ids = (const int*)  d_in[4];
    float*       out        = (float*)d_out;

    cudaFuncSetAttribute(pnn_mma_kernel,
                         cudaFuncAttributeMaxDynamicSharedMemorySize, AT_BYTES);

    precompute_kernel<<<9, 256>>>(embeds, W_hidden, b_hidden, anchor_ids);

    cudaLaunchConfig_t cfg = {};
    cfg.gridDim  = dim3(N_NODES / 32, 1, 1);
    cfg.blockDim = dim3(256, 1, 1);
    cfg.dynamicSmemBytes = AT_BYTES;
    cfg.stream = 0;
    cudaLaunchAttribute attr[1];
    attr[0].id = cudaLaunchAttributeProgrammaticStreamSerialization;
    attr[0].val.programmaticStreamSerializationAllowed = 1;
    cfg.attrs = attr;
    cfg.numAttrs = 1;

    cudaError_t e = cudaLaunchKernelEx(&cfg, pnn_mma_kernel, dists, out);
    if (e != cudaSuccess) {
        pnn_mma_kernel<<<N_NODES / 32, 256, AT_BYTES>>>(dists, out);
    }
}